// round 2
// baseline (speedup 1.0000x reference)
#include <cuda_runtime.h>
#include <cuda_fp16.h>

#define B_    32
#define NIN   2048
#define DIN   16
#define J_    64
#define C_    32
#define ITERS 5
#define EPS_  1e-7f

#define RT    512        // routing threads per block
#define ROWH  40         // padded halfs per smem row (32 + 8) = 80 bytes

// u_hat in fp16, layout [b][j][i][c]  (256 MB device-global scratch)
__device__ __half g_uhat[(size_t)B_ * J_ * NIN * C_];

// ---------------------------------------------------------------------------
// Stage 1: u_hat[b,j,i,c] = sum_d W[i,j,c,d] * x[b,i,d]
// One block per i. Reads W exactly once (268 MB), writes fp16 u_hat (134 MB).
// ---------------------------------------------------------------------------
__global__ void __launch_bounds__(256) uhat_kernel(const float* __restrict__ x,
                                                   const float* __restrict__ W)
{
    __shared__ float4 us4[B_][DIN / 4];   // u[b][d] for this i
    const int i   = blockIdx.x;
    const int tid = threadIdx.x;

    // load u slice: x[(b*NIN + i)*DIN + d], 512 floats
    for (int t = tid; t < B_ * DIN; t += 256) {
        int b = t / DIN, d = t % DIN;
        ((float*)us4)[t] = x[((size_t)b * NIN + i) * DIN + d];
    }
    __syncthreads();

    const int warp = tid >> 5;
    const int lane = tid & 31;            // lane == c

    #pragma unroll
    for (int jo = 0; jo < 2; jo++) {
        const int jbase = warp * 8 + jo * 4;
        // W registers for 4 j values: W[i, j, lane, 0..15]
        float4 wr[4][4];
        #pragma unroll
        for (int jj = 0; jj < 4; jj++) {
            const float4* wp = (const float4*)(W + (((size_t)i * J_ + jbase + jj) * C_ + lane) * DIN);
            #pragma unroll
            for (int k = 0; k < 4; k++) wr[jj][k] = wp[k];
        }
        #pragma unroll 4
        for (int b = 0; b < B_; b++) {
            float acc0 = 0.f, acc1 = 0.f, acc2 = 0.f, acc3 = 0.f;
            #pragma unroll
            for (int k = 0; k < 4; k++) {
                float4 u4 = us4[b][k];   // broadcast LDS.128
                acc0 += wr[0][k].x*u4.x + wr[0][k].y*u4.y + wr[0][k].z*u4.z + wr[0][k].w*u4.w;
                acc1 += wr[1][k].x*u4.x + wr[1][k].y*u4.y + wr[1][k].z*u4.z + wr[1][k].w*u4.w;
                acc2 += wr[2][k].x*u4.x + wr[2][k].y*u4.y + wr[2][k].z*u4.z + wr[2][k].w*u4.w;
                acc3 += wr[3][k].x*u4.x + wr[3][k].y*u4.y + wr[3][k].z*u4.z + wr[3][k].w*u4.w;
            }
            size_t base = (((size_t)b * J_ + jbase) * NIN + i) * C_ + lane;
            g_uhat[base + 0 * (size_t)NIN * C_] = __float2half_rn(acc0);
            g_uhat[base + 1 * (size_t)NIN * C_] = __float2half_rn(acc1);
            g_uhat[base + 2 * (size_t)NIN * C_] = __float2half_rn(acc2);
            g_uhat[base + 3 * (size_t)NIN * C_] = __float2half_rn(acc3);
        }
    }
}

// ---------------------------------------------------------------------------
// Stage 2: routing. One block per (b,j). u_hat slice resident in SMEM (fp16,
// 80B-padded rows). All 5 iterations fully on-chip.
// ---------------------------------------------------------------------------
__global__ void __launch_bounds__(RT) routing_kernel(float* __restrict__ out)
{
    extern __shared__ __half u_s[];       // [NIN][ROWH] halfs = 160 KB
    __shared__ float bb[NIN];             // routing logits
    __shared__ float wexp[NIN];           // exp(b - m), unnormalized weights
    __shared__ float part[32][C_ + 1];    // s partials [ig][c]
    __shared__ float red[16];
    __shared__ float m_sh, z_sh;
    __shared__ __half2 v2_sh[C_ / 2];

    const int tid = threadIdx.x;
    const int bj  = blockIdx.x;           // bj = b*J_ + j
    const int warp = tid >> 5, lane = tid & 31;

    // --- load u_hat slice (contiguous 128 KB) into padded SMEM rows ---
    {
        const uint4* src = (const uint4*)(g_uhat + (size_t)bj * (NIN * C_));
        for (int g = tid; g < NIN * C_ / 8; g += RT) {   // 16B chunks
            int i = g >> 2, cp = g & 3;
            uint4 v = src[g];
            *(uint4*)(u_s + i * ROWH + cp * 8) = v;
        }
    }
    for (int i = tid; i < NIN; i += RT) bb[i] = 0.f;
    __syncthreads();

    for (int it = 0; it < ITERS; it++) {
        // ---- block max of bb ----
        float mloc = -1e30f;
        #pragma unroll
        for (int k = 0; k < NIN / RT; k++) mloc = fmaxf(mloc, bb[tid + k * RT]);
        #pragma unroll
        for (int o = 16; o > 0; o >>= 1) mloc = fmaxf(mloc, __shfl_xor_sync(~0u, mloc, o));
        if (lane == 0) red[warp] = mloc;
        __syncthreads();
        if (warp == 0) {
            float mm = (lane < 16) ? red[lane] : -1e30f;
            #pragma unroll
            for (int o = 8; o > 0; o >>= 1) mm = fmaxf(mm, __shfl_xor_sync(~0u, mm, o));
            if (lane == 0) m_sh = mm;
        }
        __syncthreads();

        // ---- weights + Z ----
        const float m = m_sh;
        float zloc = 0.f;
        #pragma unroll
        for (int k = 0; k < NIN / RT; k++) {
            int i = tid + k * RT;
            float e = __expf(bb[i] - m);
            wexp[i] = e;
            zloc += e;
        }
        #pragma unroll
        for (int o = 16; o > 0; o >>= 1) zloc += __shfl_xor_sync(~0u, zloc, o);
        if (lane == 0) red[warp] = zloc;
        __syncthreads();
        if (warp == 0) {
            float zz = (lane < 16) ? red[lane] : 0.f;
            #pragma unroll
            for (int o = 8; o > 0; o >>= 1) zz += __shfl_xor_sync(~0u, zz, o);
            if (lane == 0) z_sh = zz;
        }
        __syncthreads();

        // ---- s-pass: s[c] = sum_i w[i] * u_hat[i][c]  (unnormalized) ----
        {
            const int c2 = tid & 15;      // half2 column
            const int ig = tid >> 4;      // i-group (0..31)
            float sx = 0.f, sy = 0.f;
            #pragma unroll 8
            for (int k = 0; k < NIN / 32; k++) {
                int i = ig + (k << 5);
                float wi = wexp[i];
                __half2 u2 = *(const __half2*)(u_s + i * ROWH + c2 * 2);
                float2 uf = __half22float2(u2);
                sx = fmaf(wi, uf.x, sx);
                sy = fmaf(wi, uf.y, sy);
            }
            part[ig][c2 * 2]     = sx;
            part[ig][c2 * 2 + 1] = sy;
        }
        __syncthreads();

        // ---- reduce partials, squash, (maybe) output ----
        if (tid < C_) {
            float sr0 = 0.f, sr1 = 0.f, sr2 = 0.f, sr3 = 0.f;
            #pragma unroll
            for (int g = 0; g < 32; g += 4) {
                sr0 += part[g + 0][tid];
                sr1 += part[g + 1][tid];
                sr2 += part[g + 2][tid];
                sr3 += part[g + 3][tid];
            }
            float s = (sr0 + sr1) + (sr2 + sr3);
            s = s / z_sh + EPS_;                    // softmax normalize + Keras eps
            float n = s * s;
            #pragma unroll
            for (int o = 16; o > 0; o >>= 1) n += __shfl_xor_sync(~0u, n, o);
            float v = s * (n / (1.f + n) * rsqrtf(n));   // squash
            if (it == ITERS - 1) {
                out[(size_t)bj * C_ + tid] = v;
            } else {
                // pack v into half2 (lanes 0..15 gather pairs via shfl)
                float va = __shfl_sync(~0u, v, 2 * lane);
                float vb = __shfl_sync(~0u, v, 2 * lane + 1);
                if (lane < 16) v2_sh[lane] = __floats2half2_rn(va, vb);
            }
        }
        __syncthreads();
        if (it == ITERS - 1) return;

        // ---- b update: b[i] += <v, u_hat[i]> ----
        {
            __half2 vh[16];
            #pragma unroll
            for (int q = 0; q < 16; q++) vh[q] = v2_sh[q];
            #pragma unroll
            for (int k = 0; k < NIN / RT; k++) {
                int i = tid + k * RT;
                const uint4* ur4 = (const uint4*)(u_s + i * ROWH);
                uint4 q0 = ur4[0], q1 = ur4[1], q2 = ur4[2], q3 = ur4[3];
                const __half2* h0 = (const __half2*)&q0;
                const __half2* h1 = (const __half2*)&q1;
                const __half2* h2 = (const __half2*)&q2;
                const __half2* h3 = (const __half2*)&q3;
                // 4 independent half2 accumulators (4 products each) -> fp32 combine
                __half2 a0 = __hmul2(vh[0], h0[0]);
                __half2 a1 = __hmul2(vh[4], h1[0]);
                __half2 a2 = __hmul2(vh[8], h2[0]);
                __half2 a3 = __hmul2(vh[12], h3[0]);
                #pragma unroll
                for (int q = 1; q < 4; q++) {
                    a0 = __hfma2(vh[q],      h0[q], a0);
                    a1 = __hfma2(vh[4 + q],  h1[q], a1);
                    a2 = __hfma2(vh[8 + q],  h2[q], a2);
                    a3 = __hfma2(vh[12 + q], h3[q], a3);
                }
                float2 f0 = __half22float2(a0), f1 = __half22float2(a1);
                float2 f2 = __half22float2(a2), f3 = __half22float2(a3);
                float d = ((f0.x + f0.y) + (f1.x + f1.y)) + ((f2.x + f2.y) + (f3.x + f3.y));
                bb[i] += d;
            }
        }
        __syncthreads();
    }
}

// ---------------------------------------------------------------------------
extern "C" void kernel_launch(void* const* d_in, const int* in_sizes, int n_in,
                              void* d_out, int out_size)
{
    const float* x = (const float*)d_in[0];
    const float* W = (const float*)d_in[1];
    // robustness: x has 1,048,576 elems; W has 67,108,864
    if (n_in >= 2 && in_sizes[0] > in_sizes[1]) {
        x = (const float*)d_in[1];
        W = (const float*)d_in[0];
    }

    const int dyn_smem = NIN * ROWH * (int)sizeof(__half);  // 163840 B
    cudaFuncSetAttribute(routing_kernel,
                         cudaFuncAttributeMaxDynamicSharedMemorySize, dyn_smem);

    uhat_kernel<<<NIN, 256>>>(x, W);
    routing_kernel<<<B_ * J_, RT, dyn_smem>>>((float*)d_out);

    (void)out_size;
}

// round 3
// speedup vs baseline: 1.3612x; 1.3612x over previous
#include <cuda_runtime.h>
#include <cuda_fp16.h>

#define B_    32
#define NIN   2048
#define DIN   16
#define J_    64
#define C_    32
#define ITERS 5
#define EPS_  1e-7f

#define RTC   512        // routing threads per CTA
#define NLOC  1024       // i-rows per CTA (NIN/2, cluster split)
#define ROWH  40         // padded halfs per smem row (80 bytes) -> conflict-free LDS.128

#define FMA_F32X2(d, a, b, c) \
    asm("fma.rn.f32x2 %0, %1, %2, %3;" : "=l"(d) : "l"(a), "l"(b), "l"(c))

// u_hat in fp16, layout [b][j][i][c]  (256 MB device-global scratch)
__device__ __half g_uhat[(size_t)B_ * J_ * NIN * C_];

__device__ __forceinline__ unsigned smem_u32(const void* p) {
    unsigned a;
    asm("{ .reg .u64 t; cvta.to.shared.u64 t, %1; cvt.u32.u64 %0, t; }" : "=r"(a) : "l"(p));
    return a;
}

// ---------------------------------------------------------------------------
// Stage 1: u_hat[b,j,i,c] = sum_d W[i,j,c,d] * x[b,i,d]
// One block per i. f32x2 packed FMA over d-pairs (d contiguous in W and u).
// ---------------------------------------------------------------------------
__global__ void __launch_bounds__(256, 2) uhat_kernel(const float* __restrict__ x,
                                                      const float* __restrict__ W)
{
    __shared__ float4 us4[B_][DIN / 4];   // u[b][d] for this i (64B-aligned rows)
    const int i   = blockIdx.x;
    const int tid = threadIdx.x;

    for (int t = tid; t < B_ * DIN; t += 256) {
        int b = t / DIN, d = t % DIN;
        ((float*)us4)[t] = x[((size_t)b * NIN + i) * DIN + d];
    }
    __syncthreads();

    const int warp = tid >> 5;
    const int lane = tid & 31;            // lane == c

    #pragma unroll
    for (int jo = 0; jo < 2; jo++) {
        const int jbase = warp * 8 + jo * 4;
        // W as packed d-pairs: wq[jj][q] = {W[..,2q], W[..,2q+1]}
        unsigned long long wq[4][8];
        #pragma unroll
        for (int jj = 0; jj < 4; jj++) {
            const ulonglong2* wp =
                (const ulonglong2*)(W + (((size_t)i * J_ + jbase + jj) * C_ + lane) * DIN);
            #pragma unroll
            for (int q2 = 0; q2 < 4; q2++) {
                ulonglong2 v = wp[q2];
                wq[jj][q2 * 2]     = v.x;
                wq[jj][q2 * 2 + 1] = v.y;
            }
        }
        #pragma unroll 4
        for (int b = 0; b < B_; b++) {
            const ulonglong2* up2 = (const ulonglong2*)&us4[b][0];
            unsigned long long up[8];
            #pragma unroll
            for (int q2 = 0; q2 < 4; q2++) {
                ulonglong2 v = up2[q2];     // LDS.128 broadcast
                up[q2 * 2]     = v.x;
                up[q2 * 2 + 1] = v.y;
            }
            unsigned long long acc[4] = {0ull, 0ull, 0ull, 0ull};  // {0.f,0.f}
            #pragma unroll
            for (int q = 0; q < 8; q++) {
                FMA_F32X2(acc[0], wq[0][q], up[q], acc[0]);
                FMA_F32X2(acc[1], wq[1][q], up[q], acc[1]);
                FMA_F32X2(acc[2], wq[2][q], up[q], acc[2]);
                FMA_F32X2(acc[3], wq[3][q], up[q], acc[3]);
            }
            size_t base = (((size_t)b * J_ + jbase) * NIN + i) * C_ + lane;
            #pragma unroll
            for (int jj = 0; jj < 4; jj++) {
                float2 f = *(float2*)&acc[jj];
                g_uhat[base + (size_t)jj * NIN * C_] = __float2half_rn(f.x + f.y);
            }
        }
    }
}

// ---------------------------------------------------------------------------
// Stage 2: routing. 2-CTA cluster per (b,j); each CTA owns NLOC=1024 i-rows
// in SMEM. No max-subtraction; exp+Z fused into the b-update pass.
// Cross-CTA per iteration: 32-float s-partial + Z via DSMEM + 1 cluster.sync.
// ---------------------------------------------------------------------------
__global__ void __launch_bounds__(RTC, 2) __cluster_dims__(2, 1, 1)
routing_kernel(float* __restrict__ out)
{
    extern __shared__ __half u_s[];           // [NLOC][ROWH] halfs = 80 KB
    __shared__ float bb[NLOC];
    __shared__ float wexp[NLOC];
    __shared__ float part[32][C_ + 1];
    __shared__ float red[16];
    __shared__ float zloc_sh;
    __shared__ float ex_s[ITERS][C_ + 1];     // written by PEER
    __shared__ float ex_z[ITERS];             // written by PEER
    __shared__ __half2 v2_sh[C_ / 2];

    const int tid  = threadIdx.x;
    const int warp = tid >> 5, lane = tid & 31;
    unsigned rank;
    asm("mov.u32 %0, %%cluster_ctarank;" : "=r"(rank));
    const int bj = blockIdx.x >> 1;           // cluster id = (b*J_ + j)

    // peer addresses for the exchange buffers
    unsigned exs_loc = smem_u32(&ex_s[0][0]);
    unsigned exz_loc = smem_u32(&ex_z[0]);
    unsigned peer = rank ^ 1u;
    unsigned exs_peer, exz_peer;
    asm("mapa.shared::cluster.u32 %0, %1, %2;" : "=r"(exs_peer) : "r"(exs_loc), "r"(peer));
    asm("mapa.shared::cluster.u32 %0, %1, %2;" : "=r"(exz_peer) : "r"(exz_loc), "r"(peer));

    // --- load this CTA's u_hat half (contiguous 64 KB) into padded SMEM ---
    {
        const uint4* src = (const uint4*)(g_uhat + ((size_t)bj * NIN + rank * NLOC) * C_);
        #pragma unroll
        for (int g = tid; g < NLOC * C_ / 8; g += RTC) {
            int i = g >> 2, cp = g & 3;
            *(uint4*)(u_s + i * ROWH + cp * 8) = src[g];
        }
    }
    for (int i = tid; i < NLOC; i += RTC) { bb[i] = 0.f; wexp[i] = 1.f; }
    if (tid == 0) zloc_sh = (float)NLOC;
    __syncthreads();

    for (int it = 0; it < ITERS; it++) {
        // ---- warp0 finishes Z reduction from previous b-update ----
        if (warp == 0 && it > 0) {
            float zz = (lane < 16) ? red[lane] : 0.f;
            #pragma unroll
            for (int o = 8; o > 0; o >>= 1) zz += __shfl_xor_sync(~0u, zz, o);
            if (lane == 0) zloc_sh = zz;
        }

        // ---- s-pass: partial s[c] over local i's (unnormalized) ----
        {
            const int c2 = tid & 15;
            const int ig = tid >> 4;
            float sx = 0.f, sy = 0.f;
            #pragma unroll 8
            for (int k = 0; k < NLOC / 32; k++) {
                int i = ig + (k << 5);
                float wi = wexp[i];
                float2 uf = __half22float2(*(const __half2*)(u_s + i * ROWH + c2 * 2));
                sx = fmaf(wi, uf.x, sx);
                sy = fmaf(wi, uf.y, sy);
            }
            part[ig][c2 * 2]     = sx;
            part[ig][c2 * 2 + 1] = sy;
        }
        __syncthreads();

        // ---- reduce partials; send to peer ----
        float s_own = 0.f;
        if (tid < C_) {
            float sr0 = 0.f, sr1 = 0.f, sr2 = 0.f, sr3 = 0.f;
            #pragma unroll
            for (int g = 0; g < 32; g += 4) {
                sr0 += part[g + 0][tid];
                sr1 += part[g + 1][tid];
                sr2 += part[g + 2][tid];
                sr3 += part[g + 3][tid];
            }
            s_own = (sr0 + sr1) + (sr2 + sr3);
            unsigned dst = exs_peer + (it * (C_ + 1) + tid) * 4;
            asm volatile("st.shared::cluster.f32 [%0], %1;" :: "r"(dst), "f"(s_own) : "memory");
            if (tid == 0)
                asm volatile("st.shared::cluster.f32 [%0], %1;"
                             :: "r"(exz_peer + it * 4), "f"(zloc_sh) : "memory");
        }
        asm volatile("barrier.cluster.arrive.aligned;" ::: "memory");
        asm volatile("barrier.cluster.wait.aligned;"   ::: "memory");

        // ---- combine, softmax-normalize, squash ----
        if (tid < C_) {
            float s = (s_own + ex_s[it][tid]) / (zloc_sh + ex_z[it]) + EPS_;
            float n = s * s;
            #pragma unroll
            for (int o = 16; o > 0; o >>= 1) n += __shfl_xor_sync(~0u, n, o);
            float v = s * (n / (1.f + n) * rsqrtf(n));
            if (it == ITERS - 1) {
                if (rank == 0) out[(size_t)bj * C_ + tid] = v;
            } else {
                float va = __shfl_sync(~0u, v, 2 * lane);
                float vb = __shfl_sync(~0u, v, 2 * lane + 1);
                if (lane < 16) v2_sh[lane] = __floats2half2_rn(va, vb);
            }
        }
        __syncthreads();
        if (it == ITERS - 1) return;

        // ---- b-update + exp + local Z partial (fused) ----
        {
            __half2 vh[16];
            #pragma unroll
            for (int q = 0; q < 16; q++) vh[q] = v2_sh[q];
            float zl = 0.f;
            #pragma unroll
            for (int k = 0; k < NLOC / RTC; k++) {
                int i = tid + k * RTC;
                const uint4* ur4 = (const uint4*)(u_s + i * ROWH);
                uint4 q0 = ur4[0], q1 = ur4[1], q2 = ur4[2], q3 = ur4[3];
                const __half2* h0 = (const __half2*)&q0;
                const __half2* h1 = (const __half2*)&q1;
                const __half2* h2 = (const __half2*)&q2;
                const __half2* h3 = (const __half2*)&q3;
                __half2 a0 = __hmul2(vh[0],  h0[0]);
                __half2 a1 = __hmul2(vh[4],  h1[0]);
                __half2 a2 = __hmul2(vh[8],  h2[0]);
                __half2 a3 = __hmul2(vh[12], h3[0]);
                #pragma unroll
                for (int q = 1; q < 4; q++) {
                    a0 = __hfma2(vh[q],      h0[q], a0);
                    a1 = __hfma2(vh[4 + q],  h1[q], a1);
                    a2 = __hfma2(vh[8 + q],  h2[q], a2);
                    a3 = __hfma2(vh[12 + q], h3[q], a3);
                }
                float2 f0 = __half22float2(a0), f1 = __half22float2(a1);
                float2 f2 = __half22float2(a2), f3 = __half22float2(a3);
                float nb = bb[i] + (((f0.x + f0.y) + (f1.x + f1.y)) +
                                    ((f2.x + f2.y) + (f3.x + f3.y)));
                bb[i] = nb;
                float e = __expf(nb);      // no max-subtraction (|b| bounded ~20)
                wexp[i] = e;
                zl += e;
            }
            #pragma unroll
            for (int o = 16; o > 0; o >>= 1) zl += __shfl_xor_sync(~0u, zl, o);
            if (lane == 0) red[warp] = zl;
        }
        __syncthreads();   // red ready; warp0 folds it into zloc_sh at loop top
    }
}

// ---------------------------------------------------------------------------
extern "C" void kernel_launch(void* const* d_in, const int* in_sizes, int n_in,
                              void* d_out, int out_size)
{
    const float* x = (const float*)d_in[0];
    const float* W = (const float*)d_in[1];
    if (n_in >= 2 && in_sizes[0] > in_sizes[1]) {   // robustness to input order
        x = (const float*)d_in[1];
        W = (const float*)d_in[0];
    }

    const int dyn_smem = NLOC * ROWH * (int)sizeof(__half);  // 81920 B
    cudaFuncSetAttribute(routing_kernel,
                         cudaFuncAttributeMaxDynamicSharedMemorySize, dyn_smem);

    uhat_kernel<<<NIN, 256>>>(x, W);
    routing_kernel<<<B_ * J_ * 2, RTC, dyn_smem>>>((float*)d_out);

    (void)out_size;
}

// round 4
// speedup vs baseline: 1.4544x; 1.0685x over previous
#include <cuda_runtime.h>
#include <cuda_fp16.h>

#define B_    32
#define NIN   2048
#define DIN   16
#define J_    64
#define C_    32
#define ITERS 5
#define EPS_  1e-7f

#define RTC   512        // routing threads per CTA
#define NLOC  1024       // i-rows per CTA (NIN/2, 2-CTA cluster)
#define ROWH  40         // padded halfs per row (80 B): stride 20 banks -> conflict-free

#define FMA_F32X2(d, a, b, c) \
    asm("fma.rn.f32x2 %0, %1, %2, %3;" : "=l"(d) : "l"(a), "l"(b), "l"(c))

// u_hat fp16, layout [b][j][i][c]  (256 MB scratch)
__device__ __half g_uhat[(size_t)B_ * J_ * NIN * C_];

__device__ __forceinline__ unsigned smem_u32(const void* p) {
    unsigned a;
    asm("{ .reg .u64 t; cvta.to.shared.u64 t, %1; cvt.u32.u64 %0, t; }" : "=r"(a) : "l"(p));
    return a;
}
__device__ __forceinline__ __half2 u2h2(unsigned x) { return *(__half2*)&x; }

// ---------------------------------------------------------------------------
// Stage 1: u_hat[b,j,i,c] = sum_d W[i,j,c,d] * x[b,i,d].  One block per i.
// f32x2 FMA over d-pairs; each thread -> 2 j x 2 c, half2 stores.
// ---------------------------------------------------------------------------
__global__ void __launch_bounds__(256, 2) uhat_kernel(const float* __restrict__ x,
                                                      const float* __restrict__ W)
{
    __shared__ float4 us4[B_][DIN / 4];
    const int i   = blockIdx.x;
    const int tid = threadIdx.x;

    for (int t = tid; t < B_ * DIN; t += 256) {
        int b = t / DIN, d = t % DIN;
        ((float*)us4)[t] = x[((size_t)b * NIN + i) * DIN + d];
    }
    __syncthreads();

    const int warp = tid >> 5;
    const int lane = tid & 31;
    const int c2   = lane & 15;           // c pair: columns {2c2, 2c2+1}
    const int jsel = lane >> 4;           // 0..1

    #pragma unroll
    for (int jo = 0; jo < 2; jo++) {
        const int j0 = warp * 8 + jo * 4 + jsel * 2;
        // W for 2 j x 2 c rows, packed d-pairs
        unsigned long long wq[2][2][8];
        #pragma unroll
        for (int jj = 0; jj < 2; jj++) {
            const ulonglong2* wp =
                (const ulonglong2*)(W + (((size_t)i * J_ + j0 + jj) * C_ + 2 * c2) * DIN);
            #pragma unroll
            for (int q2 = 0; q2 < 4; q2++) {          // c row 0 (16 floats)
                ulonglong2 v = wp[q2];
                wq[jj][0][q2 * 2] = v.x;  wq[jj][0][q2 * 2 + 1] = v.y;
            }
            #pragma unroll
            for (int q2 = 0; q2 < 4; q2++) {          // c row 1
                ulonglong2 v = wp[4 + q2];
                wq[jj][1][q2 * 2] = v.x;  wq[jj][1][q2 * 2 + 1] = v.y;
            }
        }
        #pragma unroll 4
        for (int b = 0; b < B_; b++) {
            const ulonglong2* up2 = (const ulonglong2*)&us4[b][0];
            unsigned long long up[8];
            #pragma unroll
            for (int q2 = 0; q2 < 4; q2++) {
                ulonglong2 v = up2[q2];
                up[q2 * 2] = v.x;  up[q2 * 2 + 1] = v.y;
            }
            unsigned long long acc[2][2] = {{0ull, 0ull}, {0ull, 0ull}};
            #pragma unroll
            for (int q = 0; q < 8; q++) {
                FMA_F32X2(acc[0][0], wq[0][0][q], up[q], acc[0][0]);
                FMA_F32X2(acc[0][1], wq[0][1][q], up[q], acc[0][1]);
                FMA_F32X2(acc[1][0], wq[1][0][q], up[q], acc[1][0]);
                FMA_F32X2(acc[1][1], wq[1][1][q], up[q], acc[1][1]);
            }
            #pragma unroll
            for (int jj = 0; jj < 2; jj++) {
                float2 fa = *(float2*)&acc[jj][0];
                float2 fb = *(float2*)&acc[jj][1];
                __half2 h = __floats2half2_rn(fa.x + fa.y, fb.x + fb.y);
                *(__half2*)(g_uhat + (((size_t)b * J_ + j0 + jj) * NIN + i) * C_ + 2 * c2) = h;
            }
        }
    }
}

// ---------------------------------------------------------------------------
// Stage 2: routing. 2-CTA cluster per (b,j); NLOC rows/CTA in SMEM.
// b-logits in registers; max-stabilized fp16 softmax weights; HFMA2 s-pass;
// iteration-0 s fused into the load; flash-style (m,Z,s) cluster combine.
// ---------------------------------------------------------------------------
__global__ void __launch_bounds__(RTC, 2) __cluster_dims__(2, 1, 1)
routing_kernel(float* __restrict__ out)
{
    extern __shared__ __half u_s[];            // [NLOC][ROWH] = 80 KB
    __shared__ __half2 wexp2[NLOC];            // {e,e}, e = exp(b - m) <= 1
    __shared__ float part[16][32];             // per-warp s partials
    __shared__ float redz[16];
    __shared__ float redm[16];
    __shared__ float ex_s[ITERS][32];          // written by PEER
    __shared__ float ex_zm[ITERS][2];          // {Z, m} written by PEER
    __shared__ __half2 v2_sh[C_ / 2];

    const int tid  = threadIdx.x;
    const int warp = tid >> 5, lane = tid & 31;
    unsigned rank;
    asm("mov.u32 %0, %%cluster_ctarank;" : "=r"(rank));
    const int bj = blockIdx.x >> 1;

    unsigned exs_loc = smem_u32(&ex_s[0][0]);
    unsigned exz_loc = smem_u32(&ex_zm[0][0]);
    unsigned peer = rank ^ 1u;
    unsigned exs_peer, exz_peer;
    asm("mapa.shared::cluster.u32 %0, %1, %2;" : "=r"(exs_peer) : "r"(exs_loc), "r"(peer));
    asm("mapa.shared::cluster.u32 %0, %1, %2;" : "=r"(exz_peer) : "r"(exz_loc), "r"(peer));

    // ---- load u_hat half-slice + fused iteration-0 s accumulation ----
    {
        const uint4* src = (const uint4*)(g_uhat + ((size_t)bj * NIN + rank * NLOC) * C_);
        const int cp = tid & 3;
        __half2 a0 = __half2half2(__ushort_as_half(0));
        __half2 a1 = a0, a2 = a0, a3 = a0;
        #pragma unroll
        for (int k = 0; k < NLOC * C_ / 8 / RTC; k++) {      // 8
            int g = tid + k * RTC;
            uint4 q = src[g];
            int i = g >> 2;
            *(uint4*)(u_s + i * ROWH + cp * 8) = q;
            a0 = __hadd2(a0, u2h2(q.x));
            a1 = __hadd2(a1, u2h2(q.y));
            a2 = __hadd2(a2, u2h2(q.z));
            a3 = __hadd2(a3, u2h2(q.w));
        }
        float2 F0 = __half22float2(a0), F1 = __half22float2(a1);
        float2 F2 = __half22float2(a2), F3 = __half22float2(a3);
        float f[8] = {F0.x, F0.y, F1.x, F1.y, F2.x, F2.y, F3.x, F3.y};
        #pragma unroll
        for (int o = 4; o < 32; o <<= 1)
            #pragma unroll
            for (int t = 0; t < 8; t++) f[t] += __shfl_xor_sync(~0u, f[t], o);
        if (lane < 4) {
            *(float4*)&part[warp][lane * 8]     = make_float4(f[0], f[1], f[2], f[3]);
            *(float4*)&part[warp][lane * 8 + 4] = make_float4(f[4], f[5], f[6], f[7]);
        }
    }
    __syncthreads();

    // ---- it0 exchange + squash (uniform softmax: weights 1/NIN) ----
    float s_own = 0.f;
    if (tid < 32) {
        #pragma unroll
        for (int w = 0; w < 16; w++) s_own += part[w][tid];
        asm volatile("st.shared::cluster.f32 [%0], %1;"
                     :: "r"(exs_peer + tid * 4), "f"(s_own) : "memory");
    }
    asm volatile("barrier.cluster.arrive.aligned;" ::: "memory");
    asm volatile("barrier.cluster.wait.aligned;"   ::: "memory");
    if (tid < 32) {
        float s = (s_own + ex_s[0][tid]) * (1.f / (float)NIN) + EPS_;
        float n = s * s;
        #pragma unroll
        for (int o = 16; o > 0; o >>= 1) n += __shfl_xor_sync(~0u, n, o);
        float v = s * (n / (1.f + n) * rsqrtf(n));
        float va = __shfl_sync(~0u, v, 2 * lane);
        float vb = __shfl_sync(~0u, v, 2 * lane + 1);
        if (lane < 16) v2_sh[lane] = __floats2half2_rn(va, vb);
    }
    __syncthreads();

    float b0 = 0.f, b1 = 0.f;        // routing logits for rows tid, tid+RTC (registers)

    for (int it = 1; it < ITERS; it++) {
        // ---- b-update: b[i] += <v, u_hat[i]> ----
        {
            __half2 vh[16];
            const uint4* vv = (const uint4*)v2_sh;
            #pragma unroll
            for (int t = 0; t < 4; t++) {
                uint4 q = vv[t];
                vh[t * 4 + 0] = u2h2(q.x); vh[t * 4 + 1] = u2h2(q.y);
                vh[t * 4 + 2] = u2h2(q.z); vh[t * 4 + 3] = u2h2(q.w);
            }
            #pragma unroll
            for (int r = 0; r < 2; r++) {
                int i = tid + r * RTC;
                const uint4* ur4 = (const uint4*)(u_s + i * ROWH);
                uint4 q0 = ur4[0], q1 = ur4[1], q2 = ur4[2], q3 = ur4[3];
                const __half2* h0 = (const __half2*)&q0;
                const __half2* h1 = (const __half2*)&q1;
                const __half2* h2 = (const __half2*)&q2;
                const __half2* h3 = (const __half2*)&q3;
                __half2 a0 = __hmul2(vh[0],  h0[0]);
                __half2 a1 = __hmul2(vh[4],  h1[0]);
                __half2 a2 = __hmul2(vh[8],  h2[0]);
                __half2 a3 = __hmul2(vh[12], h3[0]);
                #pragma unroll
                for (int q = 1; q < 4; q++) {
                    a0 = __hfma2(vh[q],      h0[q], a0);
                    a1 = __hfma2(vh[4 + q],  h1[q], a1);
                    a2 = __hfma2(vh[8 + q],  h2[q], a2);
                    a3 = __hfma2(vh[12 + q], h3[q], a3);
                }
                float2 f0 = __half22float2(a0), f1 = __half22float2(a1);
                float2 f2 = __half22float2(a2), f3 = __half22float2(a3);
                float d = ((f0.x + f0.y) + (f1.x + f1.y)) + ((f2.x + f2.y) + (f3.x + f3.y));
                if (r == 0) b0 += d; else b1 += d;
            }
        }
        // ---- per-CTA max of b ----
        float mloc = fmaxf(b0, b1);
        #pragma unroll
        for (int o = 16; o > 0; o >>= 1) mloc = fmaxf(mloc, __shfl_xor_sync(~0u, mloc, o));
        if (lane == 0) redm[warp] = mloc;
        __syncthreads();
        float m = redm[0];
        #pragma unroll
        for (int w = 1; w < 16; w++) m = fmaxf(m, redm[w]);

        // ---- exp (stabilized, fits fp16) + Z partial ----
        {
            __half he0 = __float2half_rn(__expf(b0 - m));
            __half he1 = __float2half_rn(__expf(b1 - m));
            wexp2[tid]       = __half2half2(he0);
            wexp2[tid + RTC] = __half2half2(he1);
            float zl = __half2float(he0) + __half2float(he1);
            #pragma unroll
            for (int o = 16; o > 0; o >>= 1) zl += __shfl_xor_sync(~0u, zl, o);
            if (lane == 0) redz[warp] = zl;
        }
        __syncthreads();

        // ---- s-pass: HFMA2, LDS.128 rows ----
        {
            const int chunk = lane >> 3;      // 0..3 -> columns chunk*8..+7
            const int rsub  = lane & 7;
            __half2 s0 = __half2half2(__ushort_as_half(0));
            __half2 s1 = s0, s2 = s0, s3 = s0;
            #pragma unroll
            for (int k = 0; k < NLOC / 128; k++) {
                int i = warp * 8 + rsub + k * 128;
                __half2 w2 = wexp2[i];
                uint4 q = *(const uint4*)(u_s + i * ROWH + chunk * 8);
                s0 = __hfma2(w2, u2h2(q.x), s0);
                s1 = __hfma2(w2, u2h2(q.y), s1);
                s2 = __hfma2(w2, u2h2(q.z), s2);
                s3 = __hfma2(w2, u2h2(q.w), s3);
            }
            float2 F0 = __half22float2(s0), F1 = __half22float2(s1);
            float2 F2 = __half22float2(s2), F3 = __half22float2(s3);
            float f[8] = {F0.x, F0.y, F1.x, F1.y, F2.x, F2.y, F3.x, F3.y};
            #pragma unroll
            for (int o = 1; o < 8; o <<= 1)
                #pragma unroll
                for (int t = 0; t < 8; t++) f[t] += __shfl_xor_sync(~0u, f[t], o);
            if (rsub == 0) {
                *(float4*)&part[warp][chunk * 8]     = make_float4(f[0], f[1], f[2], f[3]);
                *(float4*)&part[warp][chunk * 8 + 4] = make_float4(f[4], f[5], f[6], f[7]);
            }
        }
        __syncthreads();

        // ---- exchange (s, Z, m) with peer ----
        float z = 0.f;
        if (tid < 32) {
            s_own = 0.f;
            #pragma unroll
            for (int w = 0; w < 16; w++) { s_own += part[w][tid]; z += redz[w]; }
            asm volatile("st.shared::cluster.f32 [%0], %1;"
                         :: "r"(exs_peer + (it * 32 + tid) * 4), "f"(s_own) : "memory");
            if (lane == 0)
                asm volatile("st.shared::cluster.f32 [%0], %1;"
                             :: "r"(exz_peer + (it * 2 + 0) * 4), "f"(z) : "memory");
            if (lane == 1)
                asm volatile("st.shared::cluster.f32 [%0], %1;"
                             :: "r"(exz_peer + (it * 2 + 1) * 4), "f"(m) : "memory");
        }
        asm volatile("barrier.cluster.arrive.aligned;" ::: "memory");
        asm volatile("barrier.cluster.wait.aligned;"   ::: "memory");

        // ---- combine (flash-style rescale), softmax-normalize, squash ----
        if (tid < 32) {
            float zp = ex_zm[it][0], mp = ex_zm[it][1];
            float M  = fmaxf(m, mp);
            float al = __expf(m - M), ap = __expf(mp - M);
            float s = (al * s_own + ap * ex_s[it][tid]) / (al * z + ap * zp) + EPS_;
            float n = s * s;
            #pragma unroll
            for (int o = 16; o > 0; o >>= 1) n += __shfl_xor_sync(~0u, n, o);
            float v = s * (n / (1.f + n) * rsqrtf(n));
            if (it == ITERS - 1) {
                if (rank == 0) out[(size_t)bj * C_ + tid] = v;
            } else {
                float va = __shfl_sync(~0u, v, 2 * lane);
                float vb = __shfl_sync(~0u, v, 2 * lane + 1);
                if (lane < 16) v2_sh[lane] = __floats2half2_rn(va, vb);
            }
        }
        __syncthreads();
    }
}

// ---------------------------------------------------------------------------
extern "C" void kernel_launch(void* const* d_in, const int* in_sizes, int n_in,
                              void* d_out, int out_size)
{
    const float* x = (const float*)d_in[0];
    const float* W = (const float*)d_in[1];
    if (n_in >= 2 && in_sizes[0] > in_sizes[1]) {
        x = (const float*)d_in[1];
        W = (const float*)d_in[0];
    }

    const int dyn_smem = NLOC * ROWH * (int)sizeof(__half);   // 81920 B
    cudaFuncSetAttribute(routing_kernel,
                         cudaFuncAttributeMaxDynamicSharedMemorySize, dyn_smem);

    uhat_kernel<<<NIN, 256>>>(x, W);
    routing_kernel<<<B_ * J_ * 2, RTC, dyn_smem>>>((float*)d_out);

    (void)out_size;
}

// round 5
// speedup vs baseline: 1.6459x; 1.1317x over previous
#include <cuda_runtime.h>
#include <cuda_fp16.h>

#define B_    32
#define NIN   2048
#define DIN   16
#define J_    64
#define C_    32
#define ITERS 5
#define EPS_  1e-7f

#define RT    512        // routing threads per CTA (1 CTA per (b,j), rows in registers)

#define FMA_F32X2(d, a, b, c) \
    asm("fma.rn.f32x2 %0, %1, %2, %3;" : "=l"(d) : "l"(a), "l"(b), "l"(c))

// u_hat fp16, layout [b][j][i][c]  (256 MB scratch)
__device__ __half g_uhat[(size_t)B_ * J_ * NIN * C_];

__device__ __forceinline__ __half2 u2h2(unsigned x) { return *(__half2*)&x; }

// ---------------------------------------------------------------------------
// Stage 1: u_hat[b,j,i,c] = sum_d W[i,j,c,d] * x[b,i,d].  One block per i.
// f32x2 FMA over d-pairs; thread = (1 j x 4 contiguous c) -> STG.64 stores.
// ---------------------------------------------------------------------------
__global__ void __launch_bounds__(256, 2) uhat_kernel(const float* __restrict__ x,
                                                      const float* __restrict__ W)
{
    __shared__ float4 us4[B_][DIN / 4];
    const int i   = blockIdx.x;
    const int tid = threadIdx.x;

    for (int t = tid; t < B_ * DIN; t += 256) {
        int b = t / DIN, d = t % DIN;
        ((float*)us4)[t] = x[((size_t)b * NIN + i) * DIN + d];
    }
    __syncthreads();

    const int warp = tid >> 5;
    const int lane = tid & 31;
    const int c4   = lane & 7;          // c block: 4*c4 .. 4*c4+3
    const int jq   = lane >> 3;         // 0..3

    #pragma unroll
    for (int jo = 0; jo < 2; jo++) {
        const int j = warp * 8 + jo * 4 + jq;
        // W for 4 contiguous c rows (256 B), packed as d-pairs
        unsigned long long wq[4][8];
        #pragma unroll
        for (int rr = 0; rr < 4; rr++) {
            const ulonglong2* wp =
                (const ulonglong2*)(W + (((size_t)i * J_ + j) * C_ + 4 * c4 + rr) * DIN);
            #pragma unroll
            for (int q2 = 0; q2 < 4; q2++) {
                ulonglong2 v = wp[q2];
                wq[rr][q2 * 2] = v.x;  wq[rr][q2 * 2 + 1] = v.y;
            }
        }
        #pragma unroll 4
        for (int b = 0; b < B_; b++) {
            const ulonglong2* up2 = (const ulonglong2*)&us4[b][0];
            unsigned long long up[8];
            #pragma unroll
            for (int q2 = 0; q2 < 4; q2++) {
                ulonglong2 v = up2[q2];
                up[q2 * 2] = v.x;  up[q2 * 2 + 1] = v.y;
            }
            unsigned long long acc[4] = {0ull, 0ull, 0ull, 0ull};
            #pragma unroll
            for (int q = 0; q < 8; q++) {
                FMA_F32X2(acc[0], wq[0][q], up[q], acc[0]);
                FMA_F32X2(acc[1], wq[1][q], up[q], acc[1]);
                FMA_F32X2(acc[2], wq[2][q], up[q], acc[2]);
                FMA_F32X2(acc[3], wq[3][q], up[q], acc[3]);
            }
            float2 f0 = *(float2*)&acc[0], f1 = *(float2*)&acc[1];
            float2 f2 = *(float2*)&acc[2], f3 = *(float2*)&acc[3];
            __half2 h01 = __floats2half2_rn(f0.x + f0.y, f1.x + f1.y);
            __half2 h23 = __floats2half2_rn(f2.x + f2.y, f3.x + f3.y);
            uint2 st = make_uint2(*(unsigned*)&h01, *(unsigned*)&h23);
            *(uint2*)(g_uhat + (((size_t)b * J_ + j) * NIN + i) * C_ + 4 * c4) = st;
        }
    }
}

// ---------------------------------------------------------------------------
// Stage 2: routing, register-resident. One CTA per (b,j); each thread owns
// 4 rows (64 regs). Per iteration: fused dot + b-update + exp + weighted
// s-accumulation entirely in registers; only the s/Z/m reductions touch SMEM.
// Stabilizer = previous iteration's global max (shift-invariant softmax).
// ---------------------------------------------------------------------------
__global__ void __launch_bounds__(RT) routing_kernel(float* __restrict__ out)
{
    __shared__ __half2 part[RT][20];     // round-1 s partials, 80 B rows (conflict-free)
    __shared__ float  part3[32][33];     // round-2 partials [group][c]
    __shared__ float  redz[16], redm[16];
    __shared__ __half2 v2_sh[C_ / 2];
    __shared__ float  Msh;

    const int tid  = threadIdx.x;
    const int warp = tid >> 5, lane = tid & 31;
    const int bj   = blockIdx.x;

    // ---- load 4 rows into registers, fused iteration-0 sum ----
    uint4   row[4][4];                   // 4 rows x 64 B
    __half2 s_acc[16];
    #pragma unroll
    for (int t = 0; t < 16; t++) s_acc[t] = __half2half2(__ushort_as_half(0));
    {
        const uint4* src = (const uint4*)(g_uhat + (size_t)bj * (NIN * C_));
        #pragma unroll
        for (int k = 0; k < 4; k++) {
            #pragma unroll
            for (int c = 0; c < 4; c++) {
                uint4 q = src[(tid + k * RT) * 4 + c];
                row[k][c] = q;
                s_acc[c * 4 + 0] = __hadd2(s_acc[c * 4 + 0], u2h2(q.x));
                s_acc[c * 4 + 1] = __hadd2(s_acc[c * 4 + 1], u2h2(q.y));
                s_acc[c * 4 + 2] = __hadd2(s_acc[c * 4 + 2], u2h2(q.z));
                s_acc[c * 4 + 3] = __hadd2(s_acc[c * 4 + 3], u2h2(q.w));
            }
        }
    }

    float b[4] = {0.f, 0.f, 0.f, 0.f};
    float Mprev = 0.f;
    float z = (float)NIN;                // it0: uniform weights, Z = NIN exactly
    float mloc = 0.f;

    for (int it = 0; it < ITERS; it++) {
        // ================= s / Z / m block reduction =================
        // round 1: stash per-thread s partials
        #pragma unroll
        for (int c = 0; c < 4; c++) {
            uint4 q;
            q.x = *(unsigned*)&s_acc[c * 4 + 0];
            q.y = *(unsigned*)&s_acc[c * 4 + 1];
            q.z = *(unsigned*)&s_acc[c * 4 + 2];
            q.w = *(unsigned*)&s_acc[c * 4 + 3];
            *(uint4*)&part[tid][c * 4] = q;
        }
        // z / m warp reductions
        if (it > 0) {
            #pragma unroll
            for (int o = 16; o > 0; o >>= 1) {
                z    += __shfl_xor_sync(~0u, z, o);
                mloc  = fmaxf(mloc, __shfl_xor_sync(~0u, mloc, o));
            }
            if (lane == 0) { redz[warp] = z; redm[warp] = mloc; }
        }
        __syncthreads();

        // round 2: 512 rows -> 32 groups (two fp16 chains of 8, fp32 combine)
        {
            const int p = tid & 15, g = tid >> 4;
            __half2 a0 = part[g * 16 + 0][p];
            __half2 a1 = part[g * 16 + 8][p];
            #pragma unroll
            for (int q = 1; q < 8; q++) {
                a0 = __hadd2(a0, part[g * 16 + q][p]);
                a1 = __hadd2(a1, part[g * 16 + 8 + q][p]);
            }
            float2 F0 = __half22float2(a0), F1 = __half22float2(a1);
            part3[g][2 * p]     = F0.x + F1.x;
            part3[g][2 * p + 1] = F0.y + F1.y;
        }
        __syncthreads();

        // round 3: warp 0 finishes; squash; broadcast v (or write out)
        if (tid < 32) {
            float s = part3[0][tid];
            #pragma unroll
            for (int g = 1; g < 32; g++) s += part3[g][tid];
            float Z, M;
            if (it == 0) { Z = (float)NIN; M = 0.f; }
            else {
                Z = redz[0]; M = redm[0];
                #pragma unroll
                for (int w = 1; w < 16; w++) { Z += redz[w]; M = fmaxf(M, redm[w]); }
            }
            float sv = s / Z + EPS_;
            float n = sv * sv;
            #pragma unroll
            for (int o = 16; o > 0; o >>= 1) n += __shfl_xor_sync(~0u, n, o);
            float v = sv * (n / (1.f + n) * rsqrtf(n));
            if (it == ITERS - 1) {
                out[(size_t)bj * C_ + tid] = v;
            } else {
                float va = __shfl_sync(~0u, v, 2 * lane);
                float vb = __shfl_sync(~0u, v, 2 * lane + 1);
                if (lane < 16) v2_sh[lane] = __floats2half2_rn(va, vb);
                if (lane == 0) Msh = M;           // stabilizer for next pass
            }
        }
        __syncthreads();
        if (it == ITERS - 1) return;

        // ================= fused register pass =================
        __half2 vh[16];
        {
            const uint4* vv = (const uint4*)v2_sh;
            #pragma unroll
            for (int t = 0; t < 4; t++) {
                uint4 q = vv[t];
                vh[t * 4 + 0] = u2h2(q.x); vh[t * 4 + 1] = u2h2(q.y);
                vh[t * 4 + 2] = u2h2(q.z); vh[t * 4 + 3] = u2h2(q.w);
            }
        }
        Mprev = Msh;
        z = 0.f; mloc = -1e30f;
        #pragma unroll
        for (int t = 0; t < 16; t++) s_acc[t] = __half2half2(__ushort_as_half(0));

        #pragma unroll
        for (int k = 0; k < 4; k++) {
            // d = <v, row_k>
            __half2 a0 = __hmul2(vh[0],  u2h2(row[k][0].x));
            __half2 a1 = __hmul2(vh[4],  u2h2(row[k][1].x));
            __half2 a2 = __hmul2(vh[8],  u2h2(row[k][2].x));
            __half2 a3 = __hmul2(vh[12], u2h2(row[k][3].x));
            a0 = __hfma2(vh[1],  u2h2(row[k][0].y), a0);
            a1 = __hfma2(vh[5],  u2h2(row[k][1].y), a1);
            a2 = __hfma2(vh[9],  u2h2(row[k][2].y), a2);
            a3 = __hfma2(vh[13], u2h2(row[k][3].y), a3);
            a0 = __hfma2(vh[2],  u2h2(row[k][0].z), a0);
            a1 = __hfma2(vh[6],  u2h2(row[k][1].z), a1);
            a2 = __hfma2(vh[10], u2h2(row[k][2].z), a2);
            a3 = __hfma2(vh[14], u2h2(row[k][3].z), a3);
            a0 = __hfma2(vh[3],  u2h2(row[k][0].w), a0);
            a1 = __hfma2(vh[7],  u2h2(row[k][1].w), a1);
            a2 = __hfma2(vh[11], u2h2(row[k][2].w), a2);
            a3 = __hfma2(vh[15], u2h2(row[k][3].w), a3);
            float2 f0 = __half22float2(a0), f1 = __half22float2(a1);
            float2 f2 = __half22float2(a2), f3 = __half22float2(a3);
            float d = ((f0.x + f0.y) + (f1.x + f1.y)) + ((f2.x + f2.y) + (f3.x + f3.y));
            b[k] += d;
            float e = __expf(b[k] - Mprev);       // bounded: b[k] <= Mprev + ~2.5
            z += e;
            mloc = fmaxf(mloc, b[k]);
            __half2 eh = __half2half2(__float2half_rn(e));
            #pragma unroll
            for (int c = 0; c < 4; c++) {
                s_acc[c * 4 + 0] = __hfma2(eh, u2h2(row[k][c].x), s_acc[c * 4 + 0]);
                s_acc[c * 4 + 1] = __hfma2(eh, u2h2(row[k][c].y), s_acc[c * 4 + 1]);
                s_acc[c * 4 + 2] = __hfma2(eh, u2h2(row[k][c].z), s_acc[c * 4 + 2]);
                s_acc[c * 4 + 3] = __hfma2(eh, u2h2(row[k][c].w), s_acc[c * 4 + 3]);
            }
        }
    }
}

// ---------------------------------------------------------------------------
extern "C" void kernel_launch(void* const* d_in, const int* in_sizes, int n_in,
                              void* d_out, int out_size)
{
    const float* x = (const float*)d_in[0];
    const float* W = (const float*)d_in[1];
    if (n_in >= 2 && in_sizes[0] > in_sizes[1]) {
        x = (const float*)d_in[1];
        W = (const float*)d_in[0];
    }

    uhat_kernel<<<NIN, 256>>>(x, W);
    routing_kernel<<<B_ * J_, RT>>>((float*)d_out);

    (void)out_size;
}